// round 3
// baseline (speedup 1.0000x reference)
#include <cuda_runtime.h>
#include <cuda_bf16.h>

#define N_GENE 4762
#define N_CELL 847
#define D 256
#define E_MAX 200064
#define NSUB 8

// ---------------- device scratch ----------------
__device__ int   g_deg_gsrc[N_GENE];
__device__ int   g_deg_csrc[N_CELL];
__device__ float g_norm_gsrc[N_GENE];
__device__ float g_norm_cdst[N_CELL];
__device__ float g_norm_csrc[N_CELL];
__device__ float g_norm_gdst[N_GENE];
__device__ int   g_subdeg_c[N_CELL * NSUB];
__device__ int   g_subdeg_g[N_GENE * NSUB];
__device__ int   g_offs_c[N_CELL * NSUB + 1];
__device__ int   g_offs_g[N_GENE * NSUB + 1];
__device__ int   g_cursor_c[N_CELL * NSUB];
__device__ int   g_cursor_g[N_GENE * NSUB];
__device__ int   g_csr_g2c[E_MAX];
__device__ int   g_csr_c2g[E_MAX];
__device__ float g_agg_c[N_CELL * D];
__device__ float g_agg_g[N_GENE * D];
__device__ float g_sg[N_GENE];
__device__ float g_sc[N_CELL];

// ---------------- kernels ----------------

__global__ void k_zero() {
    int i = blockIdx.x * blockDim.x + threadIdx.x;
    if (i < N_GENE) g_deg_gsrc[i] = 0;
    if (i < N_CELL) g_deg_csrc[i] = 0;
    if (i < N_CELL * NSUB) { g_subdeg_c[i] = 0; g_cursor_c[i] = 0; }
    if (i < N_GENE * NSUB) { g_subdeg_g[i] = 0; g_cursor_g[i] = 0; }
}

// Both relations; dst counts go to spread sub-bucket arrays.
__global__ void k_deg(const int* __restrict__ s1, const int* __restrict__ d1, int E1,
                      const int* __restrict__ s2, const int* __restrict__ d2, int E2) {
    int i = blockIdx.x * blockDim.x + threadIdx.x;
    if (i < E1) {
        atomicAdd(&g_deg_gsrc[s1[i]], 1);
        atomicAdd(&g_subdeg_c[d1[i] * NSUB + (i & (NSUB - 1))], 1);
    } else if (i < E1 + E2) {
        int j = i - E1;
        atomicAdd(&g_deg_csrc[s2[j]], 1);
        atomicAdd(&g_subdeg_g[d2[j] * NSUB + (j & (NSUB - 1))], 1);
    }
}

// Two blocks: 0 -> cell offsets (NSUB*N_CELL), 1 -> gene offsets.
// Two-pass per-thread (sum, then write) + shfl block scan. Also computes norms.
__global__ void k_scan() {
    int b = blockIdx.x, tid = threadIdx.x;
    int nsubs; const int* deg; int* offs;
    if (b == 0) { nsubs = N_CELL * NSUB; deg = g_subdeg_c; offs = g_offs_c; }
    else        { nsubs = N_GENE * NSUB; deg = g_subdeg_g; offs = g_offs_g; }

    int seg = (nsubs + 1023) >> 10;
    int beg = tid * seg;
    int end = beg + seg; if (end > nsubs) end = nsubs;

    int run = 0;
    for (int i = beg; i < end; i++) run += deg[i];

    int lane = tid & 31, w = tid >> 5;
    int incl = run;
#pragma unroll
    for (int o = 1; o < 32; o <<= 1) {
        int v = __shfl_up_sync(0xffffffffu, incl, o);
        if (lane >= o) incl += v;
    }
    __shared__ int wsum[32];
    __shared__ int total;
    if (lane == 31) wsum[w] = incl;
    __syncthreads();
    if (w == 0) {
        int v = wsum[lane];
        int inc2 = v;
#pragma unroll
        for (int o = 1; o < 32; o <<= 1) {
            int t = __shfl_up_sync(0xffffffffu, inc2, o);
            if (lane >= o) inc2 += t;
        }
        wsum[lane] = inc2 - v;
        if (lane == 31) total = inc2;
    }
    __syncthreads();

    int off = wsum[w] + (incl - run);   // exclusive base for this thread
    for (int i = beg; i < end; i++) { offs[i] = off; off += deg[i]; }
    if (tid == 0) offs[nsubs] = total;

    // norms (dst norm from sub-bucket sums; src norms from src degs)
    if (b == 0) {
        for (int i = tid; i < N_CELL; i += 1024) {
            int s = 0;
#pragma unroll
            for (int k = 0; k < NSUB; k++) s += g_subdeg_c[i * NSUB + k];
            g_norm_cdst[i] = rsqrtf(fmaxf((float)s, 1.0f));
            g_norm_csrc[i] = rsqrtf(fmaxf((float)g_deg_csrc[i], 1.0f));
        }
    } else {
        for (int i = tid; i < N_GENE; i += 1024) {
            int s = 0;
#pragma unroll
            for (int k = 0; k < NSUB; k++) s += g_subdeg_g[i * NSUB + k];
            g_norm_gdst[i] = rsqrtf(fmaxf((float)s, 1.0f));
            g_norm_gsrc[i] = rsqrtf(fmaxf((float)g_deg_gsrc[i], 1.0f));
        }
    }
}

__global__ void k_fill(const int* __restrict__ s1, const int* __restrict__ d1, int E1,
                       const int* __restrict__ s2, const int* __restrict__ d2, int E2) {
    int i = blockIdx.x * blockDim.x + threadIdx.x;
    if (i < E1) {
        int s = s1[i], d = d1[i];
        int bkt = d * NSUB + (i & (NSUB - 1));
        int p = atomicAdd(&g_cursor_c[bkt], 1);
        g_csr_g2c[g_offs_c[bkt] + p] = s;
    } else if (i < E1 + E2) {
        int j = i - E1;
        int s = s2[j], d = d2[j];
        int bkt = d * NSUB + (j & (NSUB - 1));
        int p = atomicAdd(&g_cursor_g[bkt], 1);
        g_csr_c2g[g_offs_g[bkt] + p] = s;
    }
}

// Aggregation: block = dst node (cells then genes), 128 threads, float2 per thread.
__global__ void k_agg(const float* __restrict__ gene_emb,
                      const float* __restrict__ cell_emb) {
    int b = blockIdx.x, tid = threadIdx.x;
    const float2* emb2; const int* csr; const float* nsrc;
    float2* outp; float nd; int beg, end;
    if (b < N_CELL) {
        emb2 = (const float2*)gene_emb; csr = g_csr_g2c; nsrc = g_norm_gsrc;
        beg = g_offs_c[b * NSUB]; end = g_offs_c[b * NSUB + NSUB];
        nd = g_norm_cdst[b]; outp = (float2*)(g_agg_c + b * D);
    } else {
        int r = b - N_CELL;
        emb2 = (const float2*)cell_emb; csr = g_csr_c2g; nsrc = g_norm_csrc;
        beg = g_offs_g[r * NSUB]; end = g_offs_g[r * NSUB + NSUB];
        nd = g_norm_gdst[r]; outp = (float2*)(g_agg_g + r * D);
    }

    __shared__ int   sidx[128];
    __shared__ float snrm[128];
    float ax = 0.0f, ay = 0.0f;

    for (int base = beg; base < end; base += 128) {
        int m = end - base; if (m > 128) m = 128;
        __syncthreads();
        if (tid < m) {
            int idx = csr[base + tid];
            sidx[tid] = idx * (D / 2);
            snrm[tid] = nsrc[idx];
        }
        __syncthreads();
        int j = 0;
        for (; j + 4 <= m; j += 4) {
            float2 f0 = emb2[sidx[j + 0] + tid];
            float2 f1 = emb2[sidx[j + 1] + tid];
            float2 f2 = emb2[sidx[j + 2] + tid];
            float2 f3 = emb2[sidx[j + 3] + tid];
            float n0 = snrm[j + 0], n1 = snrm[j + 1], n2 = snrm[j + 2], n3 = snrm[j + 3];
            ax = fmaf(f0.x, n0, ax); ay = fmaf(f0.y, n0, ay);
            ax = fmaf(f1.x, n1, ax); ay = fmaf(f1.y, n1, ay);
            ax = fmaf(f2.x, n2, ax); ay = fmaf(f2.y, n2, ay);
            ax = fmaf(f3.x, n3, ax); ay = fmaf(f3.y, n3, ay);
        }
        for (; j < m; j++) {
            float2 f = emb2[sidx[j] + tid];
            float nn = snrm[j];
            ax = fmaf(f.x, nn, ax); ay = fmaf(f.y, nn, ay);
        }
    }

    float2 o; o.x = ax * nd; o.y = ay * nd;
    outp[tid] = o;
}

// Combined GEMM (+bias+relu) with rowdot epilogue for the predictor.
__global__ void __launch_bounds__(256, 2)
k_gemm(const float* __restrict__ W_g2c, const float* __restrict__ b_g2c,
       const float* __restrict__ W_c2g, const float* __restrict__ b_c2g,
       const float* __restrict__ Wp,
       float* __restrict__ h_cell, float* __restrict__ h_gene) {
    const int CB = (N_CELL + 31) / 32;
    int blk = blockIdx.x, tid = threadIdx.x;

    const float* A; const float* W; const float* bias; float* O; float* sv;
    int n, row0, wpoff;
    if (blk < CB) {
        A = g_agg_c; W = W_g2c; bias = b_g2c; O = h_cell; sv = g_sc;
        n = N_CELL; row0 = blk * 32; wpoff = 256;
    } else {
        A = g_agg_g; W = W_c2g; bias = b_c2g; O = h_gene; sv = g_sg;
        n = N_GENE; row0 = (blk - CB) * 32; wpoff = 0;
    }

    __shared__ float sA[32][260];
    for (int i = tid; i < 32 * 256; i += 256) {
        int r = i >> 8, k = i & 255;
        int gr = row0 + r;
        sA[r][k] = (gr < n) ? A[gr * D + k] : 0.0f;
    }
    __syncthreads();

    float acc[32];
#pragma unroll
    for (int r = 0; r < 32; r++) acc[r] = 0.0f;

#pragma unroll 4
    for (int k = 0; k < 256; k++) {
        float w = W[k * D + tid];
#pragma unroll
        for (int r = 0; r < 32; r++) acc[r] = fmaf(sA[r][k], w, acc[r]);
    }

    float bv = bias[tid];
    float wpv = Wp[wpoff + tid];
    int lane = tid & 31, wrp = tid >> 5;
    __shared__ float sred[32][9];

#pragma unroll
    for (int r = 0; r < 32; r++) {
        int gr = row0 + r;
        float h = fmaxf(acc[r] + bv, 0.0f);
        if (gr < n) O[gr * D + tid] = h;
        float p = (gr < n) ? h * wpv : 0.0f;
#pragma unroll
        for (int o = 16; o; o >>= 1) p += __shfl_xor_sync(0xffffffffu, p, o);
        if (lane == 0) sred[r][wrp] = p;
    }
    __syncthreads();
    if (tid < 32) {
        float s = 0.0f;
#pragma unroll
        for (int w8 = 0; w8 < 8; w8++) s += sred[tid][w8];
        int gr = row0 + tid;
        if (gr < n) sv[gr] = s;
    }
}

__global__ void k_score(const int* __restrict__ dsrc, const int* __restrict__ ddst,
                        const float* __restrict__ bp, float* __restrict__ out, int E) {
    int i = blockIdx.x * blockDim.x + threadIdx.x;
    if (i >= E) return;
    out[i] = g_sg[dsrc[i]] + g_sc[ddst[i]] + bp[0];
}

// ---------------- launch ----------------
extern "C" void kernel_launch(void* const* d_in, const int* in_sizes, int n_in,
                              void* d_out, int out_size) {
    const float* gene_emb = (const float*)d_in[0];
    const float* cell_emb = (const float*)d_in[1];
    const float* W_g2c    = (const float*)d_in[2];
    const float* b_g2c    = (const float*)d_in[3];
    const float* W_c2g    = (const float*)d_in[4];
    const float* b_c2g    = (const float*)d_in[5];
    const float* Wp       = (const float*)d_in[6];
    const float* bp       = (const float*)d_in[7];
    const int* g2c_src    = (const int*)d_in[8];
    const int* g2c_dst    = (const int*)d_in[9];
    const int* c2g_src    = (const int*)d_in[10];
    const int* c2g_dst    = (const int*)d_in[11];
    const int* dec_src    = (const int*)d_in[12];
    const int* dec_dst    = (const int*)d_in[13];

    int E1 = in_sizes[8];
    int E2 = in_sizes[10];
    int E3 = in_sizes[12];

    float* out    = (float*)d_out;
    float* score  = out;
    float* h_gene = out + E3;
    float* h_cell = out + E3 + N_GENE * D;

    k_zero<<<(N_GENE * NSUB + 255) / 256, 256>>>();
    k_deg<<<(E1 + E2 + 255) / 256, 256>>>(g2c_src, g2c_dst, E1, c2g_src, c2g_dst, E2);
    k_scan<<<2, 1024>>>();
    k_fill<<<(E1 + E2 + 255) / 256, 256>>>(g2c_src, g2c_dst, E1, c2g_src, c2g_dst, E2);
    k_agg<<<N_CELL + N_GENE, 128>>>(gene_emb, cell_emb);

    const int CB = (N_CELL + 31) / 32;
    const int GB = (N_GENE + 31) / 32;
    k_gemm<<<CB + GB, 256>>>(W_g2c, b_g2c, W_c2g, b_c2g, Wp, h_cell, h_gene);

    k_score<<<(E3 + 255) / 256, 256>>>(dec_src, dec_dst, bp, score, E3);
}

// round 4
// speedup vs baseline: 1.0246x; 1.0246x over previous
#include <cuda_runtime.h>
#include <cuda_bf16.h>

#define N_GENE 4762
#define N_CELL 847
#define D 256
#define E_MAX 200064
#define NSUB 8
#define TM 64   // gemm rows per block

// ---------------- device scratch ----------------
__device__ int   g_deg_gsrc[N_GENE];
__device__ int   g_deg_csrc[N_CELL];
__device__ float g_norm_gsrc[N_GENE];
__device__ float g_norm_cdst[N_CELL];
__device__ float g_norm_csrc[N_CELL];
__device__ float g_norm_gdst[N_GENE];
__device__ int   g_subdeg_c[N_CELL * NSUB];
__device__ int   g_subdeg_g[N_GENE * NSUB];
__device__ int   g_offs_c[N_CELL * NSUB + 1];
__device__ int   g_offs_g[N_GENE * NSUB + 1];
__device__ int   g_cursor_c[N_CELL * NSUB];
__device__ int   g_cursor_g[N_GENE * NSUB];
__device__ int   g_csr_g2c[E_MAX];
__device__ int   g_csr_c2g[E_MAX];
__device__ float g_agg_c[N_CELL * D];
__device__ float g_agg_g[N_GENE * D];
__device__ float g_sg[N_GENE];
__device__ float g_sc[N_CELL];

// ---------------- f32x2 helpers ----------------
__device__ __forceinline__ unsigned long long pack2(float a) {
    unsigned long long r;
    asm("mov.b64 %0, {%1, %1};" : "=l"(r) : "f"(a));
    return r;
}
__device__ __forceinline__ void ffma2(unsigned long long& d, unsigned long long a,
                                      unsigned long long b) {
    asm("fma.rn.f32x2 %0, %1, %2, %3;" : "=l"(d) : "l"(a), "l"(b), "l"(d));
}
__device__ __forceinline__ void unpack2(unsigned long long v, float& lo, float& hi) {
    asm("mov.b64 {%0, %1}, %2;" : "=f"(lo), "=f"(hi) : "l"(v));
}

// ---------------- kernels ----------------

__global__ void k_zero() {
    int i = blockIdx.x * blockDim.x + threadIdx.x;
    if (i < N_GENE) g_deg_gsrc[i] = 0;
    if (i < N_CELL) g_deg_csrc[i] = 0;
    if (i < N_CELL * NSUB) { g_subdeg_c[i] = 0; g_cursor_c[i] = 0; }
    if (i < N_GENE * NSUB) { g_subdeg_g[i] = 0; g_cursor_g[i] = 0; }
}

__global__ void k_deg(const int* __restrict__ s1, const int* __restrict__ d1, int E1,
                      const int* __restrict__ s2, const int* __restrict__ d2, int E2) {
    int i = blockIdx.x * blockDim.x + threadIdx.x;
    if (i < E1) {
        atomicAdd(&g_deg_gsrc[s1[i]], 1);
        atomicAdd(&g_subdeg_c[d1[i] * NSUB + (i & (NSUB - 1))], 1);
    } else if (i < E1 + E2) {
        int j = i - E1;
        atomicAdd(&g_deg_csrc[s2[j]], 1);
        atomicAdd(&g_subdeg_g[d2[j] * NSUB + (j & (NSUB - 1))], 1);
    }
}

__global__ void k_scan() {
    int b = blockIdx.x, tid = threadIdx.x;
    int nsubs; const int* deg; int* offs;
    if (b == 0) { nsubs = N_CELL * NSUB; deg = g_subdeg_c; offs = g_offs_c; }
    else        { nsubs = N_GENE * NSUB; deg = g_subdeg_g; offs = g_offs_g; }

    int seg = (nsubs + 1023) >> 10;
    int beg = tid * seg;
    int end = beg + seg; if (end > nsubs) end = nsubs;

    int run = 0;
    for (int i = beg; i < end; i++) run += deg[i];

    int lane = tid & 31, w = tid >> 5;
    int incl = run;
#pragma unroll
    for (int o = 1; o < 32; o <<= 1) {
        int v = __shfl_up_sync(0xffffffffu, incl, o);
        if (lane >= o) incl += v;
    }
    __shared__ int wsum[32];
    __shared__ int total;
    if (lane == 31) wsum[w] = incl;
    __syncthreads();
    if (w == 0) {
        int v = wsum[lane];
        int inc2 = v;
#pragma unroll
        for (int o = 1; o < 32; o <<= 1) {
            int t = __shfl_up_sync(0xffffffffu, inc2, o);
            if (lane >= o) inc2 += t;
        }
        wsum[lane] = inc2 - v;
        if (lane == 31) total = inc2;
    }
    __syncthreads();

    int off = wsum[w] + (incl - run);
    for (int i = beg; i < end; i++) { offs[i] = off; off += deg[i]; }
    if (tid == 0) offs[nsubs] = total;

    if (b == 0) {
        for (int i = tid; i < N_CELL; i += 1024) {
            int s = 0;
#pragma unroll
            for (int k = 0; k < NSUB; k++) s += g_subdeg_c[i * NSUB + k];
            g_norm_cdst[i] = rsqrtf(fmaxf((float)s, 1.0f));
            g_norm_csrc[i] = rsqrtf(fmaxf((float)g_deg_csrc[i], 1.0f));
        }
    } else {
        for (int i = tid; i < N_GENE; i += 1024) {
            int s = 0;
#pragma unroll
            for (int k = 0; k < NSUB; k++) s += g_subdeg_g[i * NSUB + k];
            g_norm_gdst[i] = rsqrtf(fmaxf((float)s, 1.0f));
            g_norm_gsrc[i] = rsqrtf(fmaxf((float)g_deg_gsrc[i], 1.0f));
        }
    }
}

__global__ void k_fill(const int* __restrict__ s1, const int* __restrict__ d1, int E1,
                       const int* __restrict__ s2, const int* __restrict__ d2, int E2) {
    int i = blockIdx.x * blockDim.x + threadIdx.x;
    if (i < E1) {
        int s = s1[i], d = d1[i];
        int bkt = d * NSUB + (i & (NSUB - 1));
        int p = atomicAdd(&g_cursor_c[bkt], 1);
        g_csr_g2c[g_offs_c[bkt] + p] = s;
    } else if (i < E1 + E2) {
        int j = i - E1;
        int s = s2[j], d = d2[j];
        int bkt = d * NSUB + (j & (NSUB - 1));
        int p = atomicAdd(&g_cursor_g[bkt], 1);
        g_csr_c2g[g_offs_g[bkt] + p] = s;
    }
}

// Aggregation: block = dst node (cells then genes), 256 threads = columns.
__global__ void k_agg(const float* __restrict__ gene_emb,
                      const float* __restrict__ cell_emb) {
    int b = blockIdx.x, tid = threadIdx.x;
    const float* emb; const int* csr; const float* nsrc;
    float* outp; float nd; int beg, end;
    if (b < N_CELL) {
        emb = gene_emb; csr = g_csr_g2c; nsrc = g_norm_gsrc;
        beg = g_offs_c[b * NSUB]; end = g_offs_c[b * NSUB + NSUB];
        nd = g_norm_cdst[b]; outp = g_agg_c + b * D;
    } else {
        int r = b - N_CELL;
        emb = cell_emb; csr = g_csr_c2g; nsrc = g_norm_csrc;
        beg = g_offs_g[r * NSUB]; end = g_offs_g[r * NSUB + NSUB];
        nd = g_norm_gdst[r]; outp = g_agg_g + r * D;
    }

    __shared__ int   sidx[256];
    __shared__ float snrm[256];
    float acc = 0.0f;

    for (int base = beg; base < end; base += 256) {
        int m = end - base; if (m > 256) m = 256;
        __syncthreads();
        if (tid < m) {
            int idx = csr[base + tid];
            sidx[tid] = idx;
            snrm[tid] = nsrc[idx];
        }
        __syncthreads();
        int j = 0;
        for (; j + 8 <= m; j += 8) {
            float f0 = emb[sidx[j + 0] * D + tid];
            float f1 = emb[sidx[j + 1] * D + tid];
            float f2 = emb[sidx[j + 2] * D + tid];
            float f3 = emb[sidx[j + 3] * D + tid];
            float f4 = emb[sidx[j + 4] * D + tid];
            float f5 = emb[sidx[j + 5] * D + tid];
            float f6 = emb[sidx[j + 6] * D + tid];
            float f7 = emb[sidx[j + 7] * D + tid];
            acc = fmaf(f0, snrm[j + 0], acc);
            acc = fmaf(f1, snrm[j + 1], acc);
            acc = fmaf(f2, snrm[j + 2], acc);
            acc = fmaf(f3, snrm[j + 3], acc);
            acc = fmaf(f4, snrm[j + 4], acc);
            acc = fmaf(f5, snrm[j + 5], acc);
            acc = fmaf(f6, snrm[j + 6], acc);
            acc = fmaf(f7, snrm[j + 7], acc);
        }
        for (; j < m; j++) acc = fmaf(emb[sidx[j] * D + tid], snrm[j], acc);
    }

    outp[tid] = acc * nd;
}

// Register-tiled GEMM: 64 rows x 256 cols per block, 256 threads,
// 8x8 micro-tile per thread, f32x2 FMA. bias+relu+rowdot epilogue.
__global__ void __launch_bounds__(256, 2)
k_gemm(const float* __restrict__ W_g2c, const float* __restrict__ b_g2c,
       const float* __restrict__ W_c2g, const float* __restrict__ b_c2g,
       const float* __restrict__ Wp,
       float* __restrict__ h_cell, float* __restrict__ h_gene) {
    const int CB = (N_CELL + TM - 1) / TM;
    int blk = blockIdx.x, tid = threadIdx.x;

    const float* A; const float* W; const float* bias; float* O; float* sv;
    int n, row0, wpoff;
    if (blk < CB) {
        A = g_agg_c; W = W_g2c; bias = b_g2c; O = h_cell; sv = g_sc;
        n = N_CELL; row0 = blk * TM; wpoff = 256;
    } else {
        A = g_agg_g; W = W_c2g; bias = b_c2g; O = h_gene; sv = g_sg;
        n = N_GENE; row0 = (blk - CB) * TM; wpoff = 0;
    }

    __shared__ float sA[32][TM];     // [k][row]
    __shared__ float sW[32][256];    // [k][col]

    int tx = tid & 31;       // col-group: cols tx*8 .. +8
    int ty = tid >> 5;       // row-group (=warp): rows ty*8 .. +8

    unsigned long long acc[8][4];
#pragma unroll
    for (int j = 0; j < 8; j++)
#pragma unroll
        for (int c = 0; c < 4; c++) acc[j][c] = 0ull;

    // staging roles
    int a_row  = tid >> 2;           // 0..63
    int a_kseg = (tid & 3) * 8;      // 0,8,16,24
    int w_k    = tid >> 3;           // 0..31
    int w_col  = (tid & 7) * 32;     // 0..224

    for (int kc = 0; kc < 256; kc += 32) {
        // stage A[row][kc+kseg..+8] -> sA[kseg+i][row]
        {
            int gr = row0 + a_row;
            float4 v0, v1;
            if (gr < n) {
                v0 = *(const float4*)&A[gr * D + kc + a_kseg];
                v1 = *(const float4*)&A[gr * D + kc + a_kseg + 4];
            } else {
                v0 = make_float4(0.f, 0.f, 0.f, 0.f);
                v1 = v0;
            }
            sA[a_kseg + 0][a_row] = v0.x; sA[a_kseg + 1][a_row] = v0.y;
            sA[a_kseg + 2][a_row] = v0.z; sA[a_kseg + 3][a_row] = v0.w;
            sA[a_kseg + 4][a_row] = v1.x; sA[a_kseg + 5][a_row] = v1.y;
            sA[a_kseg + 6][a_row] = v1.z; sA[a_kseg + 7][a_row] = v1.w;
        }
        // stage W[kc+w_k][w_col..+32] -> sW[w_k][w_col..]
        {
            const float4* src = (const float4*)&W[(kc + w_k) * D + w_col];
            float4* dst = (float4*)&sW[w_k][w_col];
#pragma unroll
            for (int i = 0; i < 8; i++) dst[i] = src[i];
        }
        __syncthreads();

#pragma unroll
        for (int k = 0; k < 32; k++) {
            const unsigned long long* wp2 =
                (const unsigned long long*)&sW[k][tx * 8];
            unsigned long long w0 = wp2[0], w1 = wp2[1], w2 = wp2[2], w3 = wp2[3];
            float4 av0 = *(const float4*)&sA[k][ty * 8];
            float4 av1 = *(const float4*)&sA[k][ty * 8 + 4];
            float ar[8] = {av0.x, av0.y, av0.z, av0.w, av1.x, av1.y, av1.z, av1.w};
#pragma unroll
            for (int j = 0; j < 8; j++) {
                unsigned long long a2 = pack2(ar[j]);
                ffma2(acc[j][0], a2, w0);
                ffma2(acc[j][1], a2, w1);
                ffma2(acc[j][2], a2, w2);
                ffma2(acc[j][3], a2, w3);
            }
        }
        __syncthreads();
    }

    // epilogue: bias + relu + store + rowdot(Wp)
    float bv[8], wv[8];
#pragma unroll
    for (int i = 0; i < 8; i++) {
        bv[i] = bias[tx * 8 + i];
        wv[i] = Wp[wpoff + tx * 8 + i];
    }

#pragma unroll
    for (int j = 0; j < 8; j++) {
        int gr = row0 + ty * 8 + j;
        float h[8];
#pragma unroll
        for (int c = 0; c < 4; c++) {
            float lo, hi;
            unpack2(acc[j][c], lo, hi);
            h[2 * c]     = fmaxf(lo + bv[2 * c], 0.0f);
            h[2 * c + 1] = fmaxf(hi + bv[2 * c + 1], 0.0f);
        }
        float p = 0.0f;
        if (gr < n) {
            float4* o0 = (float4*)&O[gr * D + tx * 8];
            o0[0] = make_float4(h[0], h[1], h[2], h[3]);
            o0[1] = make_float4(h[4], h[5], h[6], h[7]);
#pragma unroll
            for (int i = 0; i < 8; i++) p = fmaf(h[i], wv[i], p);
        }
#pragma unroll
        for (int o = 16; o; o >>= 1) p += __shfl_xor_sync(0xffffffffu, p, o);
        if (tx == 0 && gr < n) sv[gr] = p;
    }
}

__global__ void k_score(const int* __restrict__ dsrc, const int* __restrict__ ddst,
                        const float* __restrict__ bp, float* __restrict__ out, int E) {
    int i = blockIdx.x * blockDim.x + threadIdx.x;
    if (i >= E) return;
    out[i] = g_sg[dsrc[i]] + g_sc[ddst[i]] + bp[0];
}

// ---------------- launch ----------------
extern "C" void kernel_launch(void* const* d_in, const int* in_sizes, int n_in,
                              void* d_out, int out_size) {
    const float* gene_emb = (const float*)d_in[0];
    const float* cell_emb = (const float*)d_in[1];
    const float* W_g2c    = (const float*)d_in[2];
    const float* b_g2c    = (const float*)d_in[3];
    const float* W_c2g    = (const float*)d_in[4];
    const float* b_c2g    = (const float*)d_in[5];
    const float* Wp       = (const float*)d_in[6];
    const float* bp       = (const float*)d_in[7];
    const int* g2c_src    = (const int*)d_in[8];
    const int* g2c_dst    = (const int*)d_in[9];
    const int* c2g_src    = (const int*)d_in[10];
    const int* c2g_dst    = (const int*)d_in[11];
    const int* dec_src    = (const int*)d_in[12];
    const int* dec_dst    = (const int*)d_in[13];

    int E1 = in_sizes[8];
    int E2 = in_sizes[10];
    int E3 = in_sizes[12];

    float* out    = (float*)d_out;
    float* score  = out;
    float* h_gene = out + E3;
    float* h_cell = out + E3 + N_GENE * D;

    k_zero<<<(N_GENE * NSUB + 255) / 256, 256>>>();
    k_deg<<<(E1 + E2 + 255) / 256, 256>>>(g2c_src, g2c_dst, E1, c2g_src, c2g_dst, E2);
    k_scan<<<2, 1024>>>();
    k_fill<<<(E1 + E2 + 255) / 256, 256>>>(g2c_src, g2c_dst, E1, c2g_src, c2g_dst, E2);
    k_agg<<<N_CELL + N_GENE, 256>>>(gene_emb, cell_emb);

    const int CB = (N_CELL + TM - 1) / TM;
    const int GB = (N_GENE + TM - 1) / TM;
    k_gemm<<<CB + GB, 256>>>(W_g2c, b_g2c, W_c2g, b_c2g, Wp, h_cell, h_gene);

    k_score<<<(E3 + 255) / 256, 256>>>(dec_src, dec_dst, bp, score, E3);
}

// round 5
// speedup vs baseline: 1.0383x; 1.0133x over previous
#include <cuda_runtime.h>
#include <cuda_bf16.h>

#define N_GENE 4762
#define N_CELL 847
#define D 256
#define E_MAX 200064
#define NSUB 8
#define TM 64   // gemm rows per block

// ---------------- device scratch (zero-initialized at load; every replay
// restores the zero-invariant via cleanup in k_score) ----------------
__device__ int   g_deg_gsrc[N_GENE];
__device__ int   g_deg_csrc[N_CELL];
__device__ float g_norm_gsrc[N_GENE];
__device__ float g_norm_cdst[N_CELL];
__device__ float g_norm_csrc[N_CELL];
__device__ float g_norm_gdst[N_GENE];
__device__ int   g_subdeg_c[N_CELL * NSUB];
__device__ int   g_subdeg_g[N_GENE * NSUB];
__device__ int   g_offs_c[N_CELL * NSUB + 1];
__device__ int   g_offs_g[N_GENE * NSUB + 1];
__device__ int   g_cursor_c[N_CELL * NSUB];
__device__ int   g_cursor_g[N_GENE * NSUB];
__device__ int   g_csr_g2c[E_MAX];
__device__ int   g_csr_c2g[E_MAX];
__device__ float g_agg_c[N_CELL * D];
__device__ float g_agg_g[N_GENE * D];
__device__ float g_sg[N_GENE];
__device__ float g_sc[N_CELL];

// ---------------- f32x2 helpers ----------------
__device__ __forceinline__ unsigned long long pack2(float a) {
    unsigned long long r;
    asm("mov.b64 %0, {%1, %1};" : "=l"(r) : "f"(a));
    return r;
}
__device__ __forceinline__ void ffma2(unsigned long long& d, unsigned long long a,
                                      unsigned long long b) {
    asm("fma.rn.f32x2 %0, %1, %2, %3;" : "=l"(d) : "l"(a), "l"(b), "l"(d));
}
__device__ __forceinline__ void unpack2(unsigned long long v, float& lo, float& hi) {
    asm("mov.b64 {%0, %1}, %2;" : "=f"(lo), "=f"(hi) : "l"(v));
}

// ---------------- kernels ----------------

// Launch 1: degrees. Scratch counters are zero on entry (invariant).
__global__ void k_deg(const int* __restrict__ s1, const int* __restrict__ d1, int E1,
                      const int* __restrict__ s2, const int* __restrict__ d2, int E2) {
    int i = blockIdx.x * blockDim.x + threadIdx.x;
    if (i < E1) {
        atomicAdd(&g_deg_gsrc[s1[i]], 1);
        atomicAdd(&g_subdeg_c[d1[i] * NSUB + (i & (NSUB - 1))], 1);
    } else if (i < E1 + E2) {
        int j = i - E1;
        atomicAdd(&g_deg_csrc[s2[j]], 1);
        atomicAdd(&g_subdeg_g[d2[j] * NSUB + (j & (NSUB - 1))], 1);
    }
}

// Launch 2: prefix scan of sub-bucket degrees + norms.
__global__ void k_scan() {
    int b = blockIdx.x, tid = threadIdx.x;
    int nsubs; const int* deg; int* offs;
    if (b == 0) { nsubs = N_CELL * NSUB; deg = g_subdeg_c; offs = g_offs_c; }
    else        { nsubs = N_GENE * NSUB; deg = g_subdeg_g; offs = g_offs_g; }

    int seg = (nsubs + 1023) >> 10;
    int beg = tid * seg;
    int end = beg + seg; if (end > nsubs) end = nsubs;

    int run = 0;
    for (int i = beg; i < end; i++) run += deg[i];

    int lane = tid & 31, w = tid >> 5;
    int incl = run;
#pragma unroll
    for (int o = 1; o < 32; o <<= 1) {
        int v = __shfl_up_sync(0xffffffffu, incl, o);
        if (lane >= o) incl += v;
    }
    __shared__ int wsum[32];
    __shared__ int total;
    if (lane == 31) wsum[w] = incl;
    __syncthreads();
    if (w == 0) {
        int v = wsum[lane];
        int inc2 = v;
#pragma unroll
        for (int o = 1; o < 32; o <<= 1) {
            int t = __shfl_up_sync(0xffffffffu, inc2, o);
            if (lane >= o) inc2 += t;
        }
        wsum[lane] = inc2 - v;
        if (lane == 31) total = inc2;
    }
    __syncthreads();

    int off = wsum[w] + (incl - run);
    for (int i = beg; i < end; i++) { offs[i] = off; off += deg[i]; }
    if (tid == 0) offs[nsubs] = total;

    if (b == 0) {
        for (int i = tid; i < N_CELL; i += 1024) {
            int s = 0;
#pragma unroll
            for (int k = 0; k < NSUB; k++) s += g_subdeg_c[i * NSUB + k];
            g_norm_cdst[i] = rsqrtf(fmaxf((float)s, 1.0f));
            g_norm_csrc[i] = rsqrtf(fmaxf((float)g_deg_csrc[i], 1.0f));
        }
    } else {
        for (int i = tid; i < N_GENE; i += 1024) {
            int s = 0;
#pragma unroll
            for (int k = 0; k < NSUB; k++) s += g_subdeg_g[i * NSUB + k];
            g_norm_gdst[i] = rsqrtf(fmaxf((float)s, 1.0f));
            g_norm_gsrc[i] = rsqrtf(fmaxf((float)g_deg_gsrc[i], 1.0f));
        }
    }
}

// Launch 3: CSR fill (counting sort by dst sub-bucket).
__global__ void k_fill(const int* __restrict__ s1, const int* __restrict__ d1, int E1,
                       const int* __restrict__ s2, const int* __restrict__ d2, int E2) {
    int i = blockIdx.x * blockDim.x + threadIdx.x;
    if (i < E1) {
        int s = s1[i], d = d1[i];
        int bkt = d * NSUB + (i & (NSUB - 1));
        int p = atomicAdd(&g_cursor_c[bkt], 1);
        g_csr_g2c[g_offs_c[bkt] + p] = s;
    } else if (i < E1 + E2) {
        int j = i - E1;
        int s = s2[j], d = d2[j];
        int bkt = d * NSUB + (j & (NSUB - 1));
        int p = atomicAdd(&g_cursor_g[bkt], 1);
        g_csr_c2g[g_offs_g[bkt] + p] = s;
    }
}

// Launch 4 (profiled slot): aggregation. Block = dst node, 256 threads = cols.
// 16-deep independent-load unroll for latency cover.
__global__ void k_agg(const float* __restrict__ gene_emb,
                      const float* __restrict__ cell_emb) {
    int b = blockIdx.x, tid = threadIdx.x;
    const float* emb; const int* csr; const float* nsrc;
    float* outp; float nd; int beg, end;
    if (b < N_CELL) {
        emb = gene_emb; csr = g_csr_g2c; nsrc = g_norm_gsrc;
        beg = g_offs_c[b * NSUB]; end = g_offs_c[b * NSUB + NSUB];
        nd = g_norm_cdst[b]; outp = g_agg_c + b * D;
    } else {
        int r = b - N_CELL;
        emb = cell_emb; csr = g_csr_c2g; nsrc = g_norm_csrc;
        beg = g_offs_g[r * NSUB]; end = g_offs_g[r * NSUB + NSUB];
        nd = g_norm_gdst[r]; outp = g_agg_g + r * D;
    }

    __shared__ int   sidx[256];
    __shared__ float snrm[256];
    float acc = 0.0f;

    for (int base = beg; base < end; base += 256) {
        int m = end - base; if (m > 256) m = 256;
        __syncthreads();
        if (tid < m) {
            int idx = csr[base + tid];
            sidx[tid] = idx;
            snrm[tid] = nsrc[idx];
        }
        __syncthreads();
        int j = 0;
        for (; j + 16 <= m; j += 16) {
            float f[16];
#pragma unroll
            for (int u = 0; u < 16; u++) f[u] = emb[sidx[j + u] * D + tid];
#pragma unroll
            for (int u = 0; u < 16; u++) acc = fmaf(f[u], snrm[j + u], acc);
        }
        for (; j + 4 <= m; j += 4) {
            float f0 = emb[sidx[j + 0] * D + tid];
            float f1 = emb[sidx[j + 1] * D + tid];
            float f2 = emb[sidx[j + 2] * D + tid];
            float f3 = emb[sidx[j + 3] * D + tid];
            acc = fmaf(f0, snrm[j + 0], acc);
            acc = fmaf(f1, snrm[j + 1], acc);
            acc = fmaf(f2, snrm[j + 2], acc);
            acc = fmaf(f3, snrm[j + 3], acc);
        }
        for (; j < m; j++) acc = fmaf(emb[sidx[j] * D + tid], snrm[j], acc);
    }

    outp[tid] = acc * nd;
}

// Launch 5: register-tiled GEMM with f32x2 FMA, bias+relu+rowdot epilogue.
__global__ void __launch_bounds__(256, 2)
k_gemm(const float* __restrict__ W_g2c, const float* __restrict__ b_g2c,
       const float* __restrict__ W_c2g, const float* __restrict__ b_c2g,
       const float* __restrict__ Wp,
       float* __restrict__ h_cell, float* __restrict__ h_gene) {
    const int CB = (N_CELL + TM - 1) / TM;
    int blk = blockIdx.x, tid = threadIdx.x;

    const float* A; const float* W; const float* bias; float* O; float* sv;
    int n, row0, wpoff;
    if (blk < CB) {
        A = g_agg_c; W = W_g2c; bias = b_g2c; O = h_cell; sv = g_sc;
        n = N_CELL; row0 = blk * TM; wpoff = 256;
    } else {
        A = g_agg_g; W = W_c2g; bias = b_c2g; O = h_gene; sv = g_sg;
        n = N_GENE; row0 = (blk - CB) * TM; wpoff = 0;
    }

    __shared__ float sA[32][TM];
    __shared__ float sW[32][256];

    int tx = tid & 31;
    int ty = tid >> 5;

    unsigned long long acc[8][4];
#pragma unroll
    for (int j = 0; j < 8; j++)
#pragma unroll
        for (int c = 0; c < 4; c++) acc[j][c] = 0ull;

    int a_row  = tid >> 2;
    int a_kseg = (tid & 3) * 8;
    int w_k    = tid >> 3;
    int w_col  = (tid & 7) * 32;

    for (int kc = 0; kc < 256; kc += 32) {
        {
            int gr = row0 + a_row;
            float4 v0, v1;
            if (gr < n) {
                v0 = *(const float4*)&A[gr * D + kc + a_kseg];
                v1 = *(const float4*)&A[gr * D + kc + a_kseg + 4];
            } else {
                v0 = make_float4(0.f, 0.f, 0.f, 0.f);
                v1 = v0;
            }
            sA[a_kseg + 0][a_row] = v0.x; sA[a_kseg + 1][a_row] = v0.y;
            sA[a_kseg + 2][a_row] = v0.z; sA[a_kseg + 3][a_row] = v0.w;
            sA[a_kseg + 4][a_row] = v1.x; sA[a_kseg + 5][a_row] = v1.y;
            sA[a_kseg + 6][a_row] = v1.z; sA[a_kseg + 7][a_row] = v1.w;
        }
        {
            const float4* src = (const float4*)&W[(kc + w_k) * D + w_col];
            float4* dst = (float4*)&sW[w_k][w_col];
#pragma unroll
            for (int i = 0; i < 8; i++) dst[i] = src[i];
        }
        __syncthreads();

#pragma unroll
        for (int k = 0; k < 32; k++) {
            const unsigned long long* wp2 =
                (const unsigned long long*)&sW[k][tx * 8];
            unsigned long long w0 = wp2[0], w1 = wp2[1], w2 = wp2[2], w3 = wp2[3];
            float4 av0 = *(const float4*)&sA[k][ty * 8];
            float4 av1 = *(const float4*)&sA[k][ty * 8 + 4];
            float ar[8] = {av0.x, av0.y, av0.z, av0.w, av1.x, av1.y, av1.z, av1.w};
#pragma unroll
            for (int j = 0; j < 8; j++) {
                unsigned long long a2 = pack2(ar[j]);
                ffma2(acc[j][0], a2, w0);
                ffma2(acc[j][1], a2, w1);
                ffma2(acc[j][2], a2, w2);
                ffma2(acc[j][3], a2, w3);
            }
        }
        __syncthreads();
    }

    float bv[8], wv[8];
#pragma unroll
    for (int i = 0; i < 8; i++) {
        bv[i] = bias[tx * 8 + i];
        wv[i] = Wp[wpoff + tx * 8 + i];
    }

#pragma unroll
    for (int j = 0; j < 8; j++) {
        int gr = row0 + ty * 8 + j;
        float h[8];
#pragma unroll
        for (int c = 0; c < 4; c++) {
            float lo, hi;
            unpack2(acc[j][c], lo, hi);
            h[2 * c]     = fmaxf(lo + bv[2 * c], 0.0f);
            h[2 * c + 1] = fmaxf(hi + bv[2 * c + 1], 0.0f);
        }
        float p = 0.0f;
        if (gr < n) {
            float4* o0 = (float4*)&O[gr * D + tx * 8];
            o0[0] = make_float4(h[0], h[1], h[2], h[3]);
            o0[1] = make_float4(h[4], h[5], h[6], h[7]);
#pragma unroll
            for (int i = 0; i < 8; i++) p = fmaf(h[i], wv[i], p);
        }
#pragma unroll
        for (int o = 16; o; o >>= 1) p += __shfl_xor_sync(0xffffffffu, p, o);
        if (tx == 0 && gr < n) sv[gr] = p;
    }
}

// Launch 6: edge scores + scratch cleanup (restores zero-invariant for the
// next graph replay).
__global__ void k_score(const int* __restrict__ dsrc, const int* __restrict__ ddst,
                        const float* __restrict__ bp, float* __restrict__ out, int E) {
    int i = blockIdx.x * blockDim.x + threadIdx.x;
    if (i < E) out[i] = g_sg[dsrc[i]] + g_sc[ddst[i]] + bp[0];

    // cleanup (total threads >> cleanup elements)
    if (i < N_GENE) g_deg_gsrc[i] = 0;
    if (i < N_CELL) g_deg_csrc[i] = 0;
    if (i < N_CELL * NSUB) { g_subdeg_c[i] = 0; g_cursor_c[i] = 0; }
    if (i < N_GENE * NSUB) { g_subdeg_g[i] = 0; g_cursor_g[i] = 0; }
}

// ---------------- launch ----------------
extern "C" void kernel_launch(void* const* d_in, const int* in_sizes, int n_in,
                              void* d_out, int out_size) {
    const float* gene_emb = (const float*)d_in[0];
    const float* cell_emb = (const float*)d_in[1];
    const float* W_g2c    = (const float*)d_in[2];
    const float* b_g2c    = (const float*)d_in[3];
    const float* W_c2g    = (const float*)d_in[4];
    const float* b_c2g    = (const float*)d_in[5];
    const float* Wp       = (const float*)d_in[6];
    const float* bp       = (const float*)d_in[7];
    const int* g2c_src    = (const int*)d_in[8];
    const int* g2c_dst    = (const int*)d_in[9];
    const int* c2g_src    = (const int*)d_in[10];
    const int* c2g_dst    = (const int*)d_in[11];
    const int* dec_src    = (const int*)d_in[12];
    const int* dec_dst    = (const int*)d_in[13];

    int E1 = in_sizes[8];
    int E2 = in_sizes[10];
    int E3 = in_sizes[12];

    float* out    = (float*)d_out;
    float* score  = out;
    float* h_gene = out + E3;
    float* h_cell = out + E3 + N_GENE * D;

    k_deg<<<(E1 + E2 + 255) / 256, 256>>>(g2c_src, g2c_dst, E1, c2g_src, c2g_dst, E2);
    k_scan<<<2, 1024>>>();
    k_fill<<<(E1 + E2 + 255) / 256, 256>>>(g2c_src, g2c_dst, E1, c2g_src, c2g_dst, E2);
    k_agg<<<N_CELL + N_GENE, 256>>>(gene_emb, cell_emb);

    const int CB = (N_CELL + TM - 1) / TM;
    const int GB = (N_GENE + TM - 1) / TM;
    k_gemm<<<CB + GB, 256>>>(W_g2c, b_g2c, W_c2g, b_c2g, Wp, h_cell, h_gene);

    k_score<<<(E3 + 255) / 256, 256>>>(dec_src, dec_dst, bp, score, E3);
}

// round 6
// speedup vs baseline: 1.1135x; 1.0724x over previous
#include <cuda_runtime.h>
#include <cuda_bf16.h>

#define N_GENE 4762
#define N_CELL 847
#define D 256
#define E_MAX 200064
#define NSUB 8
#define TM 64   // gemm rows per block

// ---------------- device scratch (zero-initialized at load; every replay
// restores the zero-invariant via cleanup in k_score) ----------------
__device__ float g_norm_gsrc[N_GENE];
__device__ float g_norm_cdst[N_CELL];
__device__ float g_norm_csrc[N_CELL];
__device__ float g_norm_gdst[N_GENE];
__device__ int   g_subdeg_c[N_CELL * NSUB];    // g2c dst (cells)
__device__ int   g_subdeg_g[N_GENE * NSUB];    // c2g dst (genes)
__device__ int   g_subdeg_gsrc[N_GENE * NSUB]; // g2c src (genes)
__device__ int   g_subdeg_csrc[N_CELL * NSUB]; // c2g src (cells)
__device__ int   g_offs_c[N_CELL * NSUB + 1];
__device__ int   g_offs_g[N_GENE * NSUB + 1];
__device__ int   g_cursor_c[N_CELL * NSUB];
__device__ int   g_cursor_g[N_GENE * NSUB];
__device__ int   g_csr_g2c[E_MAX];
__device__ int   g_csr_c2g[E_MAX];
__device__ float g_agg_c[N_CELL * D];
__device__ float g_agg_g[N_GENE * D];
__device__ float g_sg[N_GENE];
__device__ float g_sc[N_CELL];

// ---------------- f32x2 helpers ----------------
__device__ __forceinline__ unsigned long long pack2(float a) {
    unsigned long long r;
    asm("mov.b64 %0, {%1, %1};" : "=l"(r) : "f"(a));
    return r;
}
__device__ __forceinline__ void ffma2(unsigned long long& d, unsigned long long a,
                                      unsigned long long b) {
    asm("fma.rn.f32x2 %0, %1, %2, %3;" : "=l"(d) : "l"(a), "l"(b), "l"(d));
}
__device__ __forceinline__ void unpack2(unsigned long long v, float& lo, float& hi) {
    asm("mov.b64 {%0, %1}, %2;" : "=f"(lo), "=f"(hi) : "l"(v));
}

// ---------------- kernels ----------------

// Launch 1: degrees — all four streams into spread sub-buckets (no hot addrs).
__global__ void k_deg(const int* __restrict__ s1, const int* __restrict__ d1, int E1,
                      const int* __restrict__ s2, const int* __restrict__ d2, int E2) {
    int i = blockIdx.x * blockDim.x + threadIdx.x;
    if (i < E1) {
        int sub = i & (NSUB - 1);
        atomicAdd(&g_subdeg_gsrc[s1[i] * NSUB + sub], 1);
        atomicAdd(&g_subdeg_c[d1[i] * NSUB + sub], 1);
    } else if (i < E1 + E2) {
        int j = i - E1;
        int sub = j & (NSUB - 1);
        atomicAdd(&g_subdeg_csrc[s2[j] * NSUB + sub], 1);
        atomicAdd(&g_subdeg_g[d2[j] * NSUB + sub], 1);
    }
}

// Launch 2: prefix scan of dst sub-bucket degrees + all four norm arrays.
__global__ void k_scan() {
    int b = blockIdx.x, tid = threadIdx.x;
    int nsubs; const int* deg; int* offs;
    if (b == 0) { nsubs = N_CELL * NSUB; deg = g_subdeg_c; offs = g_offs_c; }
    else        { nsubs = N_GENE * NSUB; deg = g_subdeg_g; offs = g_offs_g; }

    int seg = (nsubs + 1023) >> 10;
    int beg = tid * seg;
    int end = beg + seg; if (end > nsubs) end = nsubs;

    int run = 0;
    for (int i = beg; i < end; i++) run += deg[i];

    int lane = tid & 31, w = tid >> 5;
    int incl = run;
#pragma unroll
    for (int o = 1; o < 32; o <<= 1) {
        int v = __shfl_up_sync(0xffffffffu, incl, o);
        if (lane >= o) incl += v;
    }
    __shared__ int wsum[32];
    __shared__ int total;
    if (lane == 31) wsum[w] = incl;
    __syncthreads();
    if (w == 0) {
        int v = wsum[lane];
        int inc2 = v;
#pragma unroll
        for (int o = 1; o < 32; o <<= 1) {
            int t = __shfl_up_sync(0xffffffffu, inc2, o);
            if (lane >= o) inc2 += t;
        }
        wsum[lane] = inc2 - v;
        if (lane == 31) total = inc2;
    }
    __syncthreads();

    int off = wsum[w] + (incl - run);
    for (int i = beg; i < end; i++) { offs[i] = off; off += deg[i]; }
    if (tid == 0) offs[nsubs] = total;

    if (b == 0) {
        for (int i = tid; i < N_CELL; i += 1024) {
            int s0 = 0, s1 = 0;
#pragma unroll
            for (int k = 0; k < NSUB; k++) {
                s0 += g_subdeg_c[i * NSUB + k];
                s1 += g_subdeg_csrc[i * NSUB + k];
            }
            g_norm_cdst[i] = rsqrtf(fmaxf((float)s0, 1.0f));
            g_norm_csrc[i] = rsqrtf(fmaxf((float)s1, 1.0f));
        }
    } else {
        for (int i = tid; i < N_GENE; i += 1024) {
            int s0 = 0, s1 = 0;
#pragma unroll
            for (int k = 0; k < NSUB; k++) {
                s0 += g_subdeg_g[i * NSUB + k];
                s1 += g_subdeg_gsrc[i * NSUB + k];
            }
            g_norm_gdst[i] = rsqrtf(fmaxf((float)s0, 1.0f));
            g_norm_gsrc[i] = rsqrtf(fmaxf((float)s1, 1.0f));
        }
    }
}

// Launch 3: CSR fill (counting sort by dst sub-bucket).
__global__ void k_fill(const int* __restrict__ s1, const int* __restrict__ d1, int E1,
                       const int* __restrict__ s2, const int* __restrict__ d2, int E2) {
    int i = blockIdx.x * blockDim.x + threadIdx.x;
    if (i < E1) {
        int s = s1[i], d = d1[i];
        int bkt = d * NSUB + (i & (NSUB - 1));
        int p = atomicAdd(&g_cursor_c[bkt], 1);
        g_csr_g2c[g_offs_c[bkt] + p] = s;
    } else if (i < E1 + E2) {
        int j = i - E1;
        int s = s2[j], d = d2[j];
        int bkt = d * NSUB + (j & (NSUB - 1));
        int p = atomicAdd(&g_cursor_g[bkt], 1);
        g_csr_c2g[g_offs_g[bkt] + p] = s;
    }
}

// Launch 4 (profiled slot): aggregation. Block = dst node, 256 threads = cols.
// Measured AT the LTS roofline (~37us for 410MB) — leave shape alone.
__global__ void k_agg(const float* __restrict__ gene_emb,
                      const float* __restrict__ cell_emb) {
    int b = blockIdx.x, tid = threadIdx.x;
    const float* emb; const int* csr; const float* nsrc;
    float* outp; float nd; int beg, end;
    if (b < N_CELL) {
        emb = gene_emb; csr = g_csr_g2c; nsrc = g_norm_gsrc;
        beg = g_offs_c[b * NSUB]; end = g_offs_c[b * NSUB + NSUB];
        nd = g_norm_cdst[b]; outp = g_agg_c + b * D;
    } else {
        int r = b - N_CELL;
        emb = cell_emb; csr = g_csr_c2g; nsrc = g_norm_csrc;
        beg = g_offs_g[r * NSUB]; end = g_offs_g[r * NSUB + NSUB];
        nd = g_norm_gdst[r]; outp = g_agg_g + r * D;
    }

    __shared__ int   sidx[256];
    __shared__ float snrm[256];
    float acc = 0.0f;

    for (int base = beg; base < end; base += 256) {
        int m = end - base; if (m > 256) m = 256;
        __syncthreads();
        if (tid < m) {
            int idx = csr[base + tid];
            sidx[tid] = idx;
            snrm[tid] = nsrc[idx];
        }
        __syncthreads();
        int j = 0;
        for (; j + 16 <= m; j += 16) {
            float f[16];
#pragma unroll
            for (int u = 0; u < 16; u++) f[u] = emb[sidx[j + u] * D + tid];
#pragma unroll
            for (int u = 0; u < 16; u++) acc = fmaf(f[u], snrm[j + u], acc);
        }
        for (; j + 4 <= m; j += 4) {
            float f0 = emb[sidx[j + 0] * D + tid];
            float f1 = emb[sidx[j + 1] * D + tid];
            float f2 = emb[sidx[j + 2] * D + tid];
            float f3 = emb[sidx[j + 3] * D + tid];
            acc = fmaf(f0, snrm[j + 0], acc);
            acc = fmaf(f1, snrm[j + 1], acc);
            acc = fmaf(f2, snrm[j + 2], acc);
            acc = fmaf(f3, snrm[j + 3], acc);
        }
        for (; j < m; j++) acc = fmaf(emb[sidx[j] * D + tid], snrm[j], acc);
    }

    outp[tid] = acc * nd;
}

// Launch 5: register-tiled GEMM. Grid is 89 blocks (<148 SMs) -> occupancy 1
// is a full wave; allow 255 regs so the 8x8 f32x2 tile does NOT spill.
__global__ void __launch_bounds__(256, 1)
k_gemm(const float* __restrict__ W_g2c, const float* __restrict__ b_g2c,
       const float* __restrict__ W_c2g, const float* __restrict__ b_c2g,
       const float* __restrict__ Wp,
       float* __restrict__ h_cell, float* __restrict__ h_gene) {
    const int CB = (N_CELL + TM - 1) / TM;
    int blk = blockIdx.x, tid = threadIdx.x;

    const float* A; const float* W; const float* bias; float* O; float* sv;
    int n, row0, wpoff;
    if (blk < CB) {
        A = g_agg_c; W = W_g2c; bias = b_g2c; O = h_cell; sv = g_sc;
        n = N_CELL; row0 = blk * TM; wpoff = 256;
    } else {
        A = g_agg_g; W = W_c2g; bias = b_c2g; O = h_gene; sv = g_sg;
        n = N_GENE; row0 = (blk - CB) * TM; wpoff = 0;
    }

    __shared__ float sA[32][TM];
    __shared__ float sW[32][256];

    int tx = tid & 31;
    int ty = tid >> 5;

    unsigned long long acc[8][4];
#pragma unroll
    for (int j = 0; j < 8; j++)
#pragma unroll
        for (int c = 0; c < 4; c++) acc[j][c] = 0ull;

    int a_row  = tid >> 2;
    int a_kseg = (tid & 3) * 8;
    int w_k    = tid >> 3;
    int w_col  = (tid & 7) * 32;

    for (int kc = 0; kc < 256; kc += 32) {
        {
            int gr = row0 + a_row;
            float4 v0, v1;
            if (gr < n) {
                v0 = *(const float4*)&A[gr * D + kc + a_kseg];
                v1 = *(const float4*)&A[gr * D + kc + a_kseg + 4];
            } else {
                v0 = make_float4(0.f, 0.f, 0.f, 0.f);
                v1 = v0;
            }
            sA[a_kseg + 0][a_row] = v0.x; sA[a_kseg + 1][a_row] = v0.y;
            sA[a_kseg + 2][a_row] = v0.z; sA[a_kseg + 3][a_row] = v0.w;
            sA[a_kseg + 4][a_row] = v1.x; sA[a_kseg + 5][a_row] = v1.y;
            sA[a_kseg + 6][a_row] = v1.z; sA[a_kseg + 7][a_row] = v1.w;
        }
        {
            const float4* src = (const float4*)&W[(kc + w_k) * D + w_col];
            float4* dst = (float4*)&sW[w_k][w_col];
#pragma unroll
            for (int i = 0; i < 8; i++) dst[i] = src[i];
        }
        __syncthreads();

#pragma unroll
        for (int k = 0; k < 32; k++) {
            const unsigned long long* wp2 =
                (const unsigned long long*)&sW[k][tx * 8];
            unsigned long long w0 = wp2[0], w1 = wp2[1], w2 = wp2[2], w3 = wp2[3];
            float4 av0 = *(const float4*)&sA[k][ty * 8];
            float4 av1 = *(const float4*)&sA[k][ty * 8 + 4];
            float ar[8] = {av0.x, av0.y, av0.z, av0.w, av1.x, av1.y, av1.z, av1.w};
#pragma unroll
            for (int j = 0; j < 8; j++) {
                unsigned long long a2 = pack2(ar[j]);
                ffma2(acc[j][0], a2, w0);
                ffma2(acc[j][1], a2, w1);
                ffma2(acc[j][2], a2, w2);
                ffma2(acc[j][3], a2, w3);
            }
        }
        __syncthreads();
    }

    float bv[8], wv[8];
#pragma unroll
    for (int i = 0; i < 8; i++) {
        bv[i] = bias[tx * 8 + i];
        wv[i] = Wp[wpoff + tx * 8 + i];
    }

#pragma unroll
    for (int j = 0; j < 8; j++) {
        int gr = row0 + ty * 8 + j;
        float h[8];
#pragma unroll
        for (int c = 0; c < 4; c++) {
            float lo, hi;
            unpack2(acc[j][c], lo, hi);
            h[2 * c]     = fmaxf(lo + bv[2 * c], 0.0f);
            h[2 * c + 1] = fmaxf(hi + bv[2 * c + 1], 0.0f);
        }
        float p = 0.0f;
        if (gr < n) {
            float4* o0 = (float4*)&O[gr * D + tx * 8];
            o0[0] = make_float4(h[0], h[1], h[2], h[3]);
            o0[1] = make_float4(h[4], h[5], h[6], h[7]);
#pragma unroll
            for (int i = 0; i < 8; i++) p = fmaf(h[i], wv[i], p);
        }
#pragma unroll
        for (int o = 16; o; o >>= 1) p += __shfl_xor_sync(0xffffffffu, p, o);
        if (tx == 0 && gr < n) sv[gr] = p;
    }
}

// Launch 6: edge scores + scratch cleanup (restores zero-invariant).
__global__ void k_score(const int* __restrict__ dsrc, const int* __restrict__ ddst,
                        const float* __restrict__ bp, float* __restrict__ out, int E) {
    int i = blockIdx.x * blockDim.x + threadIdx.x;
    if (i < E) out[i] = g_sg[dsrc[i]] + g_sc[ddst[i]] + bp[0];

    if (i < N_CELL * NSUB) { g_subdeg_c[i] = 0; g_cursor_c[i] = 0; g_subdeg_csrc[i] = 0; }
    if (i < N_GENE * NSUB) { g_subdeg_g[i] = 0; g_cursor_g[i] = 0; g_subdeg_gsrc[i] = 0; }
}

// ---------------- launch ----------------
extern "C" void kernel_launch(void* const* d_in, const int* in_sizes, int n_in,
                              void* d_out, int out_size) {
    const float* gene_emb = (const float*)d_in[0];
    const float* cell_emb = (const float*)d_in[1];
    const float* W_g2c    = (const float*)d_in[2];
    const float* b_g2c    = (const float*)d_in[3];
    const float* W_c2g    = (const float*)d_in[4];
    const float* b_c2g    = (const float*)d_in[5];
    const float* Wp       = (const float*)d_in[6];
    const float* bp       = (const float*)d_in[7];
    const int* g2c_src    = (const int*)d_in[8];
    const int* g2c_dst    = (const int*)d_in[9];
    const int* c2g_src    = (const int*)d_in[10];
    const int* c2g_dst    = (const int*)d_in[11];
    const int* dec_src    = (const int*)d_in[12];
    const int* dec_dst    = (const int*)d_in[13];

    int E1 = in_sizes[8];
    int E2 = in_sizes[10];
    int E3 = in_sizes[12];

    float* out    = (float*)d_out;
    float* score  = out;
    float* h_gene = out + E3;
    float* h_cell = out + E3 + N_GENE * D;

    k_deg<<<(E1 + E2 + 255) / 256, 256>>>(g2c_src, g2c_dst, E1, c2g_src, c2g_dst, E2);
    k_scan<<<2, 1024>>>();
    k_fill<<<(E1 + E2 + 255) / 256, 256>>>(g2c_src, g2c_dst, E1, c2g_src, c2g_dst, E2);
    k_agg<<<N_CELL + N_GENE, 256>>>(gene_emb, cell_emb);

    const int CB = (N_CELL + TM - 1) / TM;
    const int GB = (N_GENE + TM - 1) / TM;
    k_gemm<<<CB + GB, 256>>>(W_g2c, b_g2c, W_c2g, b_c2g, Wp, h_cell, h_gene);

    k_score<<<(E3 + 255) / 256, 256>>>(dec_src, dec_dst, bp, score, E3);
}